// round 2
// baseline (speedup 1.0000x reference)
#include <cuda_runtime.h>
#include <math.h>

// Problem shape (fixed for this problem): C = 256 channels.
#define C_DIM 256
#define ROWS  32          // rows (points) per warp
#define MAX_B 1024

// Scratch (no cudaMalloc allowed): scene offsets + per-scene coord means.
__device__ int   d_off[MAX_B + 1];
__device__ float d_mean[MAX_B * 3];

__device__ __forceinline__ void warp_red2(float& a, float& b) {
#pragma unroll
    for (int o = 16; o; o >>= 1) {
        a += __shfl_xor_sync(0xffffffffu, a, o);
        b += __shfl_xor_sync(0xffffffffu, b, o);
    }
}

// ---------------------------------------------------------------------------
// Kernel 1: per-scene mean of coords + exclusive-prefix offsets of lengths.
// Auto-detects int32 vs int64 lengths (jax x64 ambiguity) via sum==N check:
// the int32 read is always in-bounds; int64 is only read once proven 64-bit.
// ---------------------------------------------------------------------------
__global__ void scene_stats_kernel(const float* __restrict__ coord,
                                   const void* __restrict__ lengths_raw,
                                   int N, int B) {
    int b = blockIdx.x;
    __shared__ long long sh_start, sh_len;
    if (threadIdx.x == 0) {
        const int* i32 = (const int*)lengths_raw;
        long long sum32 = 0;
        for (int k = 0; k < B; k++) sum32 += (long long)i32[k];
        bool is64 = (sum32 != (long long)N);
        const long long* i64 = (const long long*)lengths_raw;
        long long start = 0;
        for (int k = 0; k < b; k++)
            start += is64 ? i64[k] : (long long)i32[k];
        long long len = is64 ? i64[b] : (long long)i32[b];
        sh_start = start;
        sh_len   = len;
        d_off[b] = (int)start;
        if (b == B - 1) d_off[B] = (int)(start + len);
    }
    __syncthreads();
    long long start = sh_start, len = sh_len;

    float sx = 0.f, sy = 0.f, sz = 0.f;
    for (long long t = threadIdx.x; t < len; t += blockDim.x) {
        const float* p = coord + (start + t) * 3;
        sx += p[0]; sy += p[1]; sz += p[2];
    }
#pragma unroll
    for (int o = 16; o; o >>= 1) {
        sx += __shfl_xor_sync(0xffffffffu, sx, o);
        sy += __shfl_xor_sync(0xffffffffu, sy, o);
        sz += __shfl_xor_sync(0xffffffffu, sz, o);
    }
    __shared__ float red[8][3];
    int w = threadIdx.x >> 5, l = threadIdx.x & 31;
    if (l == 0) { red[w][0] = sx; red[w][1] = sy; red[w][2] = sz; }
    __syncthreads();
    if (threadIdx.x == 0) {
        float ax = 0.f, ay = 0.f, az = 0.f;
        int nw = (blockDim.x + 31) >> 5;
        for (int k = 0; k < nw; k++) { ax += red[k][0]; ay += red[k][1]; az += red[k][2]; }
        long long d = len > 0 ? len : 1;
        float inv = 1.0f / (float)d;
        d_mean[b * 3 + 0] = ax * inv;
        d_mean[b * 3 + 1] = ay * inv;
        d_mean[b * 3 + 2] = az * inv;
    }
}

// ---------------------------------------------------------------------------
// Kernel 2: fully fused pipeline. One warp per point, 8 channels per lane.
// Warp owns ROWS consecutive points; f = feat + gelu(LN(xyz @ W + b)) is
// recomputed per row (halo of 1) so the depthwise conv never materializes.
// Both LayerNorms use warp-shuffle reductions only (no __syncthreads).
// ---------------------------------------------------------------------------
__global__ void __launch_bounds__(256)
fused_xcpe_kernel(const float* __restrict__ feat,
                  const float* __restrict__ coord,
                  const float* __restrict__ w_xyz,  const float* __restrict__ b_xyz,
                  const float* __restrict__ g1,     const float* __restrict__ be1,
                  const float* __restrict__ w_conv, const float* __restrict__ b_conv,
                  const float* __restrict__ g2,     const float* __restrict__ be2,
                  float* __restrict__ out, int N) {
    const int lane = threadIdx.x & 31;
    const int warp = blockIdx.x * (blockDim.x >> 5) + (threadIdx.x >> 5);
    int r0 = warp * ROWS;
    if (r0 >= N) return;
    int r1 = min(r0 + ROWS, N);
    const int c0 = lane * 8;

    // Per-thread parameter registers (8 channels each).
    float wx0[8], wx1[8], wx2[8], bx[8], g1v[8], b1v[8];
    float g2v[8], b2v[8], bcv[8], wc0[8], wc1[8], wc2[8];
#define LD8(dst, ptr)                                          \
    {                                                          \
        float4 t0 = *(const float4*)((ptr) + c0);              \
        float4 t1 = *(const float4*)((ptr) + c0 + 4);          \
        dst[0] = t0.x; dst[1] = t0.y; dst[2] = t0.z; dst[3] = t0.w; \
        dst[4] = t1.x; dst[5] = t1.y; dst[6] = t1.z; dst[7] = t1.w; \
    }
    LD8(wx0, w_xyz);
    LD8(wx1, w_xyz + C_DIM);
    LD8(wx2, w_xyz + 2 * C_DIM);
    LD8(bx, b_xyz);
    LD8(g1v, g1);  LD8(b1v, be1);
    LD8(g2v, g2);  LD8(b2v, be2);
    LD8(bcv, b_conv);
#pragma unroll
    for (int j = 0; j < 8; j++) {
        wc0[j] = w_conv[(c0 + j) * 3 + 0];
        wc1[j] = w_conv[(c0 + j) * 3 + 1];
        wc2[j] = w_conv[(c0 + j) * 3 + 2];
    }

    // Scene bounds for row r0.
    int s = 0;
    while (r0 >= d_off[s + 1]) s++;
    int sb = d_off[s], se = d_off[s + 1];

    float fA[8], fB[8], fC[8], feB[8], feC[8];

    // Compute f(i) = feat(i) + gelu(LN1(xyz_c(i) @ W + b)) for scene sc.
    auto compute_f = [&](int i, int sc, float* f, float* fe) {
        float x = coord[3 * i + 0] - d_mean[sc * 3 + 0];
        float y = coord[3 * i + 1] - d_mean[sc * 3 + 1];
        float z = coord[3 * i + 2] - d_mean[sc * 3 + 2];
        const float* frow = feat + (size_t)i * C_DIM + c0;
        float4 t0 = *(const float4*)frow;
        float4 t1 = *(const float4*)(frow + 4);
        fe[0] = t0.x; fe[1] = t0.y; fe[2] = t0.z; fe[3] = t0.w;
        fe[4] = t1.x; fe[5] = t1.y; fe[6] = t1.z; fe[7] = t1.w;
        float v[8];
        float sm = 0.f, sq = 0.f;
#pragma unroll
        for (int j = 0; j < 8; j++) {
            float t = fmaf(x, wx0[j], bx[j]);
            t = fmaf(y, wx1[j], t);
            t = fmaf(z, wx2[j], t);
            v[j] = t;
            sm += t;
            sq = fmaf(t, t, sq);
        }
        warp_red2(sm, sq);
        float mu  = sm * (1.0f / C_DIM);
        float var = sq * (1.0f / C_DIM) - mu * mu;
        float rs  = rsqrtf(var + 1e-5f);
#pragma unroll
        for (int j = 0; j < 8; j++) {
            float t  = fmaf((v[j] - mu) * rs, g1v[j], b1v[j]);
            float gl = 0.5f * t * (1.0f + erff(t * 0.7071067811865475f));
            f[j] = fe[j] + gl;
        }
    };

    // Prologue: f(r0-1) (scene value irrelevant when masked at scene start)
    if (r0 > 0) {
        float dummy[8];
        compute_f(r0 - 1, s, fA, dummy);
    } else {
#pragma unroll
        for (int j = 0; j < 8; j++) fA[j] = 0.f;
    }
    compute_f(r0, s, fB, feB);

    for (int i = r0; i < r1; i++) {
        int ip = i + 1;
        int sn = s, sbn = sb, sen = se;
        if (ip < N) {
            if (ip >= se) { sn = s + 1; sbn = se; sen = d_off[sn + 1]; }
            compute_f(ip, sn, fC, feC);
        } else {
#pragma unroll
            for (int j = 0; j < 8; j++) { fC[j] = 0.f; feC[j] = 0.f; }
        }
        float mp = (i > sb)  ? 1.f : 0.f;   // prev row in same scene
        float mn = (ip < se) ? 1.f : 0.f;   // next row in same scene

        float h[8];
        float sm = 0.f, sq = 0.f;
#pragma unroll
        for (int j = 0; j < 8; j++) {
            float cv = fmaf(wc1[j], fB[j], bcv[j]);
            cv = fmaf(wc0[j], mp * fA[j], cv);
            cv = fmaf(wc2[j], mn * fC[j], cv);
            float hh = feB[j] + cv;
            h[j] = hh;
            sm += hh;
            sq = fmaf(hh, hh, sq);
        }
        warp_red2(sm, sq);
        float mu  = sm * (1.0f / C_DIM);
        float var = sq * (1.0f / C_DIM) - mu * mu;
        float rs  = rsqrtf(var + 1e-5f);

        float* orow = out + (size_t)i * C_DIM + c0;
        float4 o0, o1;
        o0.x = fmaf((h[0] - mu) * rs, g2v[0], b2v[0]);
        o0.y = fmaf((h[1] - mu) * rs, g2v[1], b2v[1]);
        o0.z = fmaf((h[2] - mu) * rs, g2v[2], b2v[2]);
        o0.w = fmaf((h[3] - mu) * rs, g2v[3], b2v[3]);
        o1.x = fmaf((h[4] - mu) * rs, g2v[4], b2v[4]);
        o1.y = fmaf((h[5] - mu) * rs, g2v[5], b2v[5]);
        o1.z = fmaf((h[6] - mu) * rs, g2v[6], b2v[6]);
        o1.w = fmaf((h[7] - mu) * rs, g2v[7], b2v[7]);
        *(float4*)orow       = o0;
        *(float4*)(orow + 4) = o1;

        // Shift pipeline state.
#pragma unroll
        for (int j = 0; j < 8; j++) { fA[j] = fB[j]; fB[j] = fC[j]; feB[j] = feC[j]; }
        s = sn; sb = sbn; se = sen;
    }
}

// ---------------------------------------------------------------------------
extern "C" void kernel_launch(void* const* d_in, const int* in_sizes, int n_in,
                              void* d_out, int out_size) {
    const float* feat   = (const float*)d_in[0];
    const float* coord  = (const float*)d_in[1];
    const void*  lens   = d_in[2];
    const float* w_xyz  = (const float*)d_in[3];
    const float* b_xyz  = (const float*)d_in[4];
    const float* g1     = (const float*)d_in[5];
    const float* be1    = (const float*)d_in[6];
    const float* w_conv = (const float*)d_in[7];
    const float* b_conv = (const float*)d_in[8];
    const float* g2     = (const float*)d_in[9];
    const float* be2    = (const float*)d_in[10];

    int N = in_sizes[0] / C_DIM;
    int B = in_sizes[2];
    if (B > MAX_B) B = MAX_B;

    scene_stats_kernel<<<B, 256>>>(coord, lens, N, B);

    int warps  = (N + ROWS - 1) / ROWS;
    int blocks = (warps + 7) / 8;
    fused_xcpe_kernel<<<blocks, 256>>>(feat, coord, w_xyz, b_xyz, g1, be1,
                                       w_conv, b_conv, g2, be2,
                                       (float*)d_out, N);
}

// round 4
// speedup vs baseline: 1.0522x; 1.0522x over previous
#include <cuda_runtime.h>
#include <math.h>

#define C_DIM 256
#define ROWS  16          // rows (points) per warp
#define MAX_B 1024

__device__ int   d_off[MAX_B + 1];
__device__ float d_mean[MAX_B * 3];

// Interleaved 2-chain butterfly reduction: the two chains are independent so
// per-level latency overlaps (~26cyc/level effective, 5 levels).
__device__ __forceinline__ void warp_red2(float& a, float& b) {
#pragma unroll
    for (int o = 16; o; o >>= 1) {
        a += __shfl_xor_sync(0xffffffffu, a, o);
        b += __shfl_xor_sync(0xffffffffu, b, o);
    }
}

// ---------------------------------------------------------------------------
// Kernel 1: per-scene mean of coords + exclusive-prefix offsets of lengths.
// Auto-detects int32 vs int64 lengths via sum==N check.
// ---------------------------------------------------------------------------
__global__ void scene_stats_kernel(const float* __restrict__ coord,
                                   const void* __restrict__ lengths_raw,
                                   int N, int B) {
    int b = blockIdx.x;
    __shared__ long long sh_start, sh_len;
    if (threadIdx.x == 0) {
        const int* i32 = (const int*)lengths_raw;
        long long sum32 = 0;
        for (int k = 0; k < B; k++) sum32 += (long long)i32[k];
        bool is64 = (sum32 != (long long)N);
        const long long* i64 = (const long long*)lengths_raw;
        long long start = 0;
        for (int k = 0; k < b; k++)
            start += is64 ? i64[k] : (long long)i32[k];
        long long len = is64 ? i64[b] : (long long)i32[b];
        sh_start = start;
        sh_len   = len;
        d_off[b] = (int)start;
        if (b == B - 1) d_off[B] = (int)(start + len);
    }
    __syncthreads();
    long long start = sh_start, len = sh_len;

    float sx = 0.f, sy = 0.f, sz = 0.f;
    for (long long t = threadIdx.x; t < len; t += blockDim.x) {
        const float* p = coord + (start + t) * 3;
        sx += p[0]; sy += p[1]; sz += p[2];
    }
#pragma unroll
    for (int o = 16; o; o >>= 1) {
        sx += __shfl_xor_sync(0xffffffffu, sx, o);
        sy += __shfl_xor_sync(0xffffffffu, sy, o);
        sz += __shfl_xor_sync(0xffffffffu, sz, o);
    }
    __shared__ float red[8][3];
    int w = threadIdx.x >> 5, l = threadIdx.x & 31;
    if (l == 0) { red[w][0] = sx; red[w][1] = sy; red[w][2] = sz; }
    __syncthreads();
    if (threadIdx.x == 0) {
        float ax = 0.f, ay = 0.f, az = 0.f;
        int nw = (blockDim.x + 31) >> 5;
        for (int k = 0; k < nw; k++) { ax += red[k][0]; ay += red[k][1]; az += red[k][2]; }
        long long d = len > 0 ? len : 1;
        float inv = 1.0f / (float)d;
        d_mean[b * 3 + 0] = ax * inv;
        d_mean[b * 3 + 1] = ay * inv;
        d_mean[b * 3 + 2] = az * inv;
    }
}

// ---------------------------------------------------------------------------
// Kernel 2: fully fused. One warp per point-row, 8 channels per lane.
// Phase-1 params (Linear+LN1) in shared memory to cut registers; phase-2
// params (conv + LN2) in registers. Shuffle-tree reductions only.
// ---------------------------------------------------------------------------
__global__ void __launch_bounds__(256, 2)
fused_xcpe_kernel(const float* __restrict__ feat,
                  const float* __restrict__ coord,
                  const float* __restrict__ w_xyz,  const float* __restrict__ b_xyz,
                  const float* __restrict__ g1,     const float* __restrict__ be1,
                  const float* __restrict__ w_conv, const float* __restrict__ b_conv,
                  const float* __restrict__ g2,     const float* __restrict__ be2,
                  float* __restrict__ out, int N) {
    // Shared: wx0 | wx1 | wx2 | bx | g1 | be1  (6 * 256 floats = 6 KB)
    __shared__ float sp[6 * C_DIM];
    for (int k = threadIdx.x; k < 6 * C_DIM; k += blockDim.x) {
        const float* src;
        int a = k >> 8, c = k & 255;
        switch (a) {
            case 0: src = w_xyz;              break;
            case 1: src = w_xyz + C_DIM;      break;
            case 2: src = w_xyz + 2 * C_DIM;  break;
            case 3: src = b_xyz;              break;
            case 4: src = g1;                 break;
            default: src = be1;               break;
        }
        sp[k] = src[c];
    }
    __syncthreads();

    const int lane = threadIdx.x & 31;
    const int warp = blockIdx.x * (blockDim.x >> 5) + (threadIdx.x >> 5);
    int r0 = warp * ROWS;
    if (r0 >= N) return;
    int r1 = min(r0 + ROWS, N);
    const int c0 = lane * 8;

    // Phase-2 params in registers.
    float g2v[8], b2v[8], bcv[8], wc0[8], wc1[8], wc2[8];
#define LD8(dst, ptr)                                          \
    {                                                          \
        float4 t0 = *(const float4*)((ptr) + c0);              \
        float4 t1 = *(const float4*)((ptr) + c0 + 4);          \
        dst[0] = t0.x; dst[1] = t0.y; dst[2] = t0.z; dst[3] = t0.w; \
        dst[4] = t1.x; dst[5] = t1.y; dst[6] = t1.z; dst[7] = t1.w; \
    }
    LD8(g2v, g2);  LD8(b2v, be2);
    LD8(bcv, b_conv);
#pragma unroll
    for (int j = 0; j < 8; j++) {
        wc0[j] = w_conv[(c0 + j) * 3 + 0];
        wc1[j] = w_conv[(c0 + j) * 3 + 1];
        wc2[j] = w_conv[(c0 + j) * 3 + 2];
    }

    // Scene bounds for row r0.
    int s = 0;
    while (r0 >= d_off[s + 1]) s++;
    int sb = d_off[s], se = d_off[s + 1];

    float fA[8], fB[8], fC[8], feB[8], feC[8];

    // f(i) = feat(i) + gelu(LN1(xyz_c(i) @ W + b)); phase-1 params from smem.
    auto compute_f = [&](int i, int sc, float* f, float* fe) {
        float x = coord[3 * i + 0] - d_mean[sc * 3 + 0];
        float y = coord[3 * i + 1] - d_mean[sc * 3 + 1];
        float z = coord[3 * i + 2] - d_mean[sc * 3 + 2];
        const float* frow = feat + (size_t)i * C_DIM + c0;
        float4 t0 = *(const float4*)frow;
        float4 t1 = *(const float4*)(frow + 4);
        fe[0] = t0.x; fe[1] = t0.y; fe[2] = t0.z; fe[3] = t0.w;
        fe[4] = t1.x; fe[5] = t1.y; fe[6] = t1.z; fe[7] = t1.w;
        float v[8];
        float sm = 0.f, sq = 0.f;
#pragma unroll
        for (int j = 0; j < 8; j++) {
            float t = fmaf(x, sp[0 * C_DIM + c0 + j], sp[3 * C_DIM + c0 + j]);
            t = fmaf(y, sp[1 * C_DIM + c0 + j], t);
            t = fmaf(z, sp[2 * C_DIM + c0 + j], t);
            v[j] = t;
            sm += t;
            sq = fmaf(t, t, sq);
        }
        warp_red2(sm, sq);
        float mu  = sm * (1.0f / C_DIM);
        float var = sq * (1.0f / C_DIM) - mu * mu;
        float rs  = rsqrtf(var + 1e-5f);
#pragma unroll
        for (int j = 0; j < 8; j++) {
            float t  = fmaf((v[j] - mu) * rs, sp[4 * C_DIM + c0 + j], sp[5 * C_DIM + c0 + j]);
            float gl = 0.5f * t * (1.0f + erff(t * 0.7071067811865475f));
            f[j] = fe[j] + gl;
        }
    };

    // Prologue.
    if (r0 > 0) {
        float dummy[8];
        compute_f(r0 - 1, s, fA, dummy);
    } else {
#pragma unroll
        for (int j = 0; j < 8; j++) fA[j] = 0.f;
    }
    compute_f(r0, s, fB, feB);

    for (int i = r0; i < r1; i++) {
        int ip = i + 1;
        int sn = s, sbn = sb, sen = se;
        if (ip < N) {
            if (ip >= se) { sn = s + 1; sbn = se; sen = d_off[sn + 1]; }
            compute_f(ip, sn, fC, feC);
        } else {
#pragma unroll
            for (int j = 0; j < 8; j++) { fC[j] = 0.f; feC[j] = 0.f; }
        }
        float mp = (i > sb)  ? 1.f : 0.f;
        float mn = (ip < se) ? 1.f : 0.f;

        float h[8];
        float sm = 0.f, sq = 0.f;
#pragma unroll
        for (int j = 0; j < 8; j++) {
            float cv = fmaf(wc1[j], fB[j], bcv[j]);
            cv = fmaf(wc0[j], mp * fA[j], cv);
            cv = fmaf(wc2[j], mn * fC[j], cv);
            float hh = feB[j] + cv;
            h[j] = hh;
            sm += hh;
            sq = fmaf(hh, hh, sq);
        }
        warp_red2(sm, sq);
        float mu  = sm * (1.0f / C_DIM);
        float var = sq * (1.0f / C_DIM) - mu * mu;
        float rs  = rsqrtf(var + 1e-5f);

        float* orow = out + (size_t)i * C_DIM + c0;
        float4 o0, o1;
        o0.x = fmaf((h[0] - mu) * rs, g2v[0], b2v[0]);
        o0.y = fmaf((h[1] - mu) * rs, g2v[1], b2v[1]);
        o0.z = fmaf((h[2] - mu) * rs, g2v[2], b2v[2]);
        o0.w = fmaf((h[3] - mu) * rs, g2v[3], b2v[3]);
        o1.x = fmaf((h[4] - mu) * rs, g2v[4], b2v[4]);
        o1.y = fmaf((h[5] - mu) * rs, g2v[5], b2v[5]);
        o1.z = fmaf((h[6] - mu) * rs, g2v[6], b2v[6]);
        o1.w = fmaf((h[7] - mu) * rs, g2v[7], b2v[7]);
        *(float4*)orow       = o0;
        *(float4*)(orow + 4) = o1;

#pragma unroll
        for (int j = 0; j < 8; j++) { fA[j] = fB[j]; fB[j] = fC[j]; feB[j] = feC[j]; }
        s = sn; sb = sbn; se = sen;
    }
}

// ---------------------------------------------------------------------------
extern "C" void kernel_launch(void* const* d_in, const int* in_sizes, int n_in,
                              void* d_out, int out_size) {
    const float* feat   = (const float*)d_in[0];
    const float* coord  = (const float*)d_in[1];
    const void*  lens   = d_in[2];
    const float* w_xyz  = (const float*)d_in[3];
    const float* b_xyz  = (const float*)d_in[4];
    const float* g1     = (const float*)d_in[5];
    const float* be1    = (const float*)d_in[6];
    const float* w_conv = (const float*)d_in[7];
    const float* b_conv = (const float*)d_in[8];
    const float* g2     = (const float*)d_in[9];
    const float* be2    = (const float*)d_in[10];

    int N = in_sizes[0] / C_DIM;
    int B = in_sizes[2];
    if (B > MAX_B) B = MAX_B;

    scene_stats_kernel<<<B, 256>>>(coord, lens, N, B);

    int warps  = (N + ROWS - 1) / ROWS;
    int blocks = (warps + 7) / 8;
    fused_xcpe_kernel<<<blocks, 256>>>(feat, coord, w_xyz, b_xyz, g1, be1,
                                       w_conv, b_conv, g2, be2,
                                       (float*)d_out, N);
}